// round 16
// baseline (speedup 1.0000x reference)
#include <cuda_runtime.h>
#include <cstdint>

#define NROWS 4096
#define DIM   512
#define LAT   128
#define TOPK  16

#define BI 128
#define BJ 128
#define KC 16
#define NCHUNK (DIM / KC)

typedef unsigned long long ull;

// -------- scratch (static __device__ arrays; no runtime allocation) --------
__device__ float g_rec_test[NROWS * DIM];
__device__ float g_rec_train[NROWS * DIM];
__device__ ull   g_xtd[DIM * NROWS];             // rec_test^T, DUPLICATED pairs (x,x)  [DIM][NROWS] float2
__device__ float g_yt_gt[DIM * NROWS];           // -(gt_vals)^T         [DIM][NROWS]
__device__ float g_yt_tr[DIM * NROWS];           // -(rec_train)^T       [DIM][NROWS]
__device__ float g_dist1[(size_t)NROWS * NROWS]; // 64 MB (positive)
__device__ float g_dist2[(size_t)NROWS * NROWS]; // 64 MB (negative)
__device__ float g_pos[NROWS];
__device__ float g_neg[NROWS];

// -------- packed f32x2 helpers --------
__device__ __forceinline__ ull f2add(ull a, ull b) {
    ull r;
    asm("add.rn.f32x2 %0, %1, %2;" : "=l"(r) : "l"(a), "l"(b));
    return r;
}

// -------- cp.async helpers (16B) --------
__device__ __forceinline__ void cpa16(void* dst, const void* src) {
    unsigned d = (unsigned)__cvta_generic_to_shared(dst);
    asm volatile("cp.async.cg.shared.global [%0], [%1], 16;" :: "r"(d), "l"(src));
}
__device__ __forceinline__ void cpa_commit() { asm volatile("cp.async.commit_group;"); }
__device__ __forceinline__ void cpa_wait1()  { asm volatile("cp.async.wait_group 1;"); }
__device__ __forceinline__ void cpa_wait0()  { asm volatile("cp.async.wait_group 0;"); }

// ---------------- GEMM: out[row,:] = lat[row,:] @ W + b ----------------
__global__ void gemm_kernel(const float* __restrict__ lat,
                            const float* __restrict__ W,
                            const float* __restrict__ b,
                            float* __restrict__ out) {
    __shared__ float s_lat[LAT];
    int row = blockIdx.x;
    int tx = threadIdx.x;                         // 0..127
    s_lat[tx] = lat[row * LAT + tx];
    __syncthreads();

    float4 acc = *(const float4*)&b[tx * 4];
    const float4* W4 = (const float4*)W;          // [LAT][DIM/4]
    #pragma unroll 8
    for (int l = 0; l < LAT; l++) {
        float a = s_lat[l];
        float4 w = W4[l * (DIM / 4) + tx];
        acc.x += a * w.x; acc.y += a * w.y; acc.z += a * w.z; acc.w += a * w.w;
    }
    *(float4*)&out[(size_t)row * DIM + tx * 4] = acc;
}

// ---------------- tiled transpose: out[d][n] = sgn * in[n][d] (float) --------
__global__ void transpose_kernel(const float* __restrict__ in,
                                 float* __restrict__ out, float sgn) {
    __shared__ float tile[32][33];
    int nb = blockIdx.x * 32;     // row (n) base
    int db = blockIdx.y * 32;     // col (d) base
    int x = threadIdx.x;          // 0..31
    int y = threadIdx.y;          // 0..7
    #pragma unroll
    for (int j = 0; j < 32; j += 8)
        tile[y + j][x] = in[(size_t)(nb + y + j) * DIM + db + x];
    __syncthreads();
    #pragma unroll
    for (int j = 0; j < 32; j += 8)
        out[(size_t)(db + y + j) * NROWS + nb + x] = sgn * tile[x][y + j];
}

// ---------------- transpose + DUPLICATE: out[d][n] = (v, v) pairs ------------
// Gives the dist kernel a MOV-free X operand: the (x,x) 64-bit pair needed by
// the packed f32x2 diff is built once here instead of 8 MOVs per thread-k.
__global__ void transpose_dup_kernel(const float* __restrict__ in,
                                     ull* __restrict__ out) {
    __shared__ float tile[32][33];
    int nb = blockIdx.x * 32;
    int db = blockIdx.y * 32;
    int x = threadIdx.x;
    int y = threadIdx.y;
    #pragma unroll
    for (int j = 0; j < 32; j += 8)
        tile[y + j][x] = in[(size_t)(nb + y + j) * DIM + db + x];
    __syncthreads();
    #pragma unroll
    for (int j = 0; j < 32; j += 8) {
        float v = tile[x][y + j];
        unsigned vi = __float_as_uint(v);
        ull p;
        asm("mov.b64 %0, {%1, %1};" : "=l"(p) : "r"(vi));
        out[(size_t)(db + y + j) * NROWS + nb + x] = p;
    }
}

// ---------------- L1 cdist, BOTH matrices in one launch (grid.z selects) ----
// X comes PRE-TRANSPOSED + PRE-DUPLICATED ((x,x) pairs in GMEM): cp.async
// straight into SMEM; the hot loop has ZERO broadcast MOVs. Y pre-transposed
// + pre-negated (float). 2-buffer cp.async pipeline (proven R13 structure).
// Compute loop: per pair, FADD2 diff + 64-bit abs-mask (2x LOP3) + FADD2 acc.
__global__ __launch_bounds__(512, 2) void dist_kernel(
    const ull* __restrict__ XTd,
    const float* __restrict__ YT1, const float* __restrict__ YT2,
    float* __restrict__ D1, float* __restrict__ D2)
{
    __shared__ __align__(16) ull   Xd[2][KC][BI];   // 32 KB (dup pairs)
    __shared__ __align__(16) float Ys[2][KC][BJ];   // 16 KB  (total 48 KB static)

    const float* YTn  = blockIdx.z ? YT2 : YT1;
    float*       Dout = blockIdx.z ? D2  : D1;

    int t  = threadIdx.x;
    int tx = t & 15;          // j-group: chunks at tx*4 and 64+tx*4
    int ty = t >> 4;          // i-group: 32 groups x 4 rows
    int i0 = blockIdx.y * BI;
    int j0 = blockIdx.x * BJ;

    int lk   = t >> 5;        // k-line within chunk (0..15)
    int lane = t & 31;

    ull acc[4][4];
    #pragma unroll
    for (int i = 0; i < 4; i++)
        #pragma unroll
        for (int jp = 0; jp < 4; jp++) acc[i][jp] = 0ULL;   // (0.0f, 0.0f)

    auto load_chunk = [&](int c, int buf) {
        size_t k = (size_t)(c * KC + lk);
        // X line: 128 ull = 1 KB; warp covers it in two 512B sweeps (2 ull/lane each)
        cpa16(&Xd[buf][lk][lane * 2],      &XTd[k * NROWS + i0 + lane * 2]);
        cpa16(&Xd[buf][lk][64 + lane * 2], &XTd[k * NROWS + i0 + 64 + lane * 2]);
        // Y line: 128 floats = 512B; one 16B segment per lane
        cpa16(&Ys[buf][lk][lane * 4],      &YTn[k * NROWS + j0 + lane * 4]);
        cpa_commit();
    };

    load_chunk(0, 0);
    load_chunk(1, 1);

    for (int c = 0; c < NCHUNK; c++) {
        int cb = c & 1;
        if (c == NCHUNK - 1) cpa_wait0(); else cpa_wait1();   // chunk c landed
        __syncthreads();

        #pragma unroll
        for (int k = 0; k < KC; k++) {
            // X: 4 pre-dup pairs (32B) = 2 LDS.128, 2 distinct addrs/warp (broadcast)
            ulonglong2 A0 = *(const ulonglong2*)&Xd[cb][k][ty * 4];
            ulonglong2 A1 = *(const ulonglong2*)&Xd[cb][k][ty * 4 + 2];
            ulonglong2 bq0 = *(const ulonglong2*)&Ys[cb][k][tx * 4];      // conflict-free
            ulonglong2 bq1 = *(const ulonglong2*)&Ys[cb][k][64 + tx * 4]; // conflict-free
            ull aa[4] = { A0.x, A0.y, A1.x, A1.y };
            ull bb[4] = { bq0.x, bq0.y, bq1.x, bq1.y };
            #pragma unroll
            for (int i = 0; i < 4; i++) {
                #pragma unroll
                for (int jp = 0; jp < 4; jp++) {
                    ull d = f2add(aa[i], bb[jp]);    // (a-b0, a-b1)  (Y pre-negated)
                    d &= 0x7FFFFFFF7FFFFFFFULL;      // packed abs (2x LOP3, alu pipe)
                    acc[i][jp] = f2add(acc[i][jp], d);
                }
            }
        }
        __syncthreads();                              // done reading buffer cb

        if (c + 2 < NCHUNK) load_chunk(c + 2, cb);    // refill drained buffer
    }

    // ---- store 4x8 tile: two 16B chunks per row at j = tx*4 and 64+tx*4 ----
    #pragma unroll
    for (int i = 0; i < 4; i++) {
        size_t rowb = (size_t)(i0 + ty * 4 + i) * NROWS + j0;
        ulonglong2 o0 = { acc[i][0], acc[i][1] };
        ulonglong2 o1 = { acc[i][2], acc[i][3] };
        *(ulonglong2*)&Dout[rowb + tx * 4]      = o0;
        *(ulonglong2*)&Dout[rowb + 64 + tx * 4] = o1;
    }
}

// ---------------- per-row top-16 -> mean of reciprocals (both matrices) -------
// 2 warps per row (2048 cols each); register-resident branch-free sorted insert
// with MLP=4 loads; per-warp sorted-16 extraction into smem; warp-merge of the
// 32 candidates. grid: (NROWS/4, 2) — y selects matrix/output. block = 256.
__device__ __forceinline__ void topk_insert(float (&best)[TOPK], float v) {
    if (v < best[TOPK - 1]) {
        #pragma unroll
        for (int i = TOPK - 1; i > 0; i--)
            best[i] = fminf(fmaxf(v, best[i - 1]), best[i]);
        best[0] = fminf(best[0], v);
    }
}

__global__ void topk_kernel(const float* __restrict__ D1, const float* __restrict__ D2,
                            float* __restrict__ pos, float* __restrict__ neg) {
    const float* Dmat = blockIdx.y ? D2 : D1;
    float*       out  = blockIdx.y ? neg : pos;

    __shared__ float cand[4][2][TOPK];

    int w    = threadIdx.x >> 5;       // warp 0..7
    int lane = threadIdx.x & 31;
    int rowLocal = w & 3;
    int half     = w >> 2;             // 0 or 1
    int row  = blockIdx.x * 4 + rowLocal;

    const float4* row4 = (const float4*)(Dmat + (size_t)row * NROWS);

    const float INF = __int_as_float(0x7f800000);
    float best[TOPK];
    #pragma unroll
    for (int i = 0; i < TOPK; i++) best[i] = INF;

    int cbase = half * 512 + lane;
    #pragma unroll
    for (int it = 0; it < 4; it++) {
        int c = cbase + it * 128;
        float4 v0 = row4[c];
        float4 v1 = row4[c + 32];
        float4 v2 = row4[c + 64];
        float4 v3 = row4[c + 96];
        topk_insert(best, v0.x); topk_insert(best, v0.y);
        topk_insert(best, v0.z); topk_insert(best, v0.w);
        topk_insert(best, v1.x); topk_insert(best, v1.y);
        topk_insert(best, v1.z); topk_insert(best, v1.w);
        topk_insert(best, v2.x); topk_insert(best, v2.y);
        topk_insert(best, v2.z); topk_insert(best, v2.w);
        topk_insert(best, v3.x); topk_insert(best, v3.y);
        topk_insert(best, v3.z); topk_insert(best, v3.w);
    }

    {
        int h = 0;
        #pragma unroll
        for (int r = 0; r < TOPK; r++) {
            float v = (h < TOPK) ? best[h] : INF;
            float m = v;
            #pragma unroll
            for (int off = 16; off; off >>= 1)
                m = fminf(m, __shfl_xor_sync(0xffffffffu, m, off));
            unsigned bal = __ballot_sync(0xffffffffu, v == m);
            if (lane == (__ffs(bal) - 1)) h++;
            if (lane == 0) cand[rowLocal][half][r] = m;
        }
    }
    __syncthreads();

    if (half == 0) {
        float v = cand[rowLocal][lane >> 4][lane & 15];
        float ssum = 0.f;
        #pragma unroll
        for (int r = 0; r < TOPK; r++) {
            float m = v;
            #pragma unroll
            for (int off = 16; off; off >>= 1)
                m = fminf(m, __shfl_xor_sync(0xffffffffu, m, off));
            unsigned bal = __ballot_sync(0xffffffffu, v == m);
            if (lane == (__ffs(bal) - 1)) v = INF;   // remove extracted value
            ssum += 1.0f / m;
        }
        if (lane == 0) out[row] = ssum * (1.0f / TOPK);
    }
}

// ---------------- final: huber(relu(neg - pos)).mean() ----------------
__global__ void final_kernel(const float* __restrict__ pos,
                             const float* __restrict__ neg,
                             float* __restrict__ out) {
    __shared__ float sred[256];
    float s = 0.f;
    for (int i = threadIdx.x; i < NROWS; i += 256) {
        float l = neg[i] - pos[i];
        l = fmaxf(l, 0.f);
        float h = (l <= 1.0f) ? 0.5f * l * l : (l - 0.5f);
        s += h;
    }
    sred[threadIdx.x] = s;
    __syncthreads();
    for (int st = 128; st; st >>= 1) {
        if (threadIdx.x < st) sred[threadIdx.x] += sred[threadIdx.x + st];
        __syncthreads();
    }
    if (threadIdx.x == 0) out[0] = sred[0] * (1.0f / NROWS);
}

// ---------------- launch ----------------
extern "C" void kernel_launch(void* const* d_in, const int* in_sizes, int n_in,
                              void* d_out, int out_size) {
    const float* gt_vals      = (const float*)d_in[0];   // [4096, 512]
    const float* train_latent = (const float*)d_in[1];   // [4096, 128]
    const float* test_latent  = (const float*)d_in[2];   // [4096, 128]
    const float* W            = (const float*)d_in[3];   // [128, 512]
    const float* b            = (const float*)d_in[4];   // [512]
    float* out = (float*)d_out;

    float *rec_test, *rec_train, *yt_gt, *yt_tr, *d1, *d2, *pos, *neg;
    ull *xtd;
    cudaGetSymbolAddress((void**)&rec_test,  g_rec_test);
    cudaGetSymbolAddress((void**)&rec_train, g_rec_train);
    cudaGetSymbolAddress((void**)&xtd,       g_xtd);
    cudaGetSymbolAddress((void**)&yt_gt,     g_yt_gt);
    cudaGetSymbolAddress((void**)&yt_tr,     g_yt_tr);
    cudaGetSymbolAddress((void**)&d1,        g_dist1);
    cudaGetSymbolAddress((void**)&d2,        g_dist2);
    cudaGetSymbolAddress((void**)&pos,       g_pos);
    cudaGetSymbolAddress((void**)&neg,       g_neg);

    // 1) decode both latents
    gemm_kernel<<<NROWS, 128>>>(test_latent,  W, b, rec_test);
    gemm_kernel<<<NROWS, 128>>>(train_latent, W, b, rec_train);

    // 2) pre-transpose: X duplicated pairs; Y negated floats
    dim3 tgrid(NROWS / 32, DIM / 32), tblk(32, 8);
    transpose_dup_kernel<<<tgrid, tblk>>>(rec_test, xtd);
    transpose_kernel<<<tgrid, tblk>>>(gt_vals,   yt_gt, -1.0f);
    transpose_kernel<<<tgrid, tblk>>>(rec_train, yt_tr, -1.0f);

    // 3) both cdist matrices in ONE launch (grid.z picks matrix)
    dim3 dgrid(NROWS / BJ, NROWS / BI, 2);
    dist_kernel<<<dgrid, 512>>>(xtd, yt_gt, yt_tr, d1, d2);

    // 4) both top-k passes in ONE launch (grid.y picks matrix)
    dim3 kgrid(NROWS / 4, 2);
    topk_kernel<<<kgrid, 256>>>(d1, d2, pos, neg);

    // 5) huber mean
    final_kernel<<<1, 256>>>(pos, neg, out);
}